// round 3
// baseline (speedup 1.0000x reference)
#include <cuda_runtime.h>
#include <math.h>

// Problem constants
#define BATCH   2
#define SEQ     2048
#define DMODEL  1024
#define NHEAD   16
#define HEADD   64
#define DFF     4096
#define MROWS   (BATCH*SEQ)        // 4096

// Scratch buffers (device globals: no allocation allowed in kernel_launch)
__device__ float g_ln1 [MROWS*DMODEL];
__device__ float g_qkv [MROWS*3*DMODEL];
__device__ float g_attn[MROWS*DMODEL];
__device__ float g_x1  [MROWS*DMODEL];
__device__ float g_ln2 [MROWS*DMODEL];
__device__ float g_fc1 [MROWS*DFF];

// ---------------------------------------------------------------------------
// LayerNorm: one block per row, 256 threads, float4 vectorized (D=1024)
// ---------------------------------------------------------------------------
__global__ __launch_bounds__(256) void ln_kernel(
    const float* __restrict__ x, const float* __restrict__ w,
    const float* __restrict__ b, float* __restrict__ out)
{
    __shared__ float redA[8], redB[8];
    int row = blockIdx.x, tid = threadIdx.x;
    const float4* xr = (const float4*)(x + (size_t)row * DMODEL);
    float4 v = xr[tid];
    float s  = v.x + v.y + v.z + v.w;
    float sq = v.x*v.x + v.y*v.y + v.z*v.z + v.w*v.w;
#pragma unroll
    for (int o = 16; o > 0; o >>= 1) {
        s  += __shfl_xor_sync(0xffffffffu, s,  o);
        sq += __shfl_xor_sync(0xffffffffu, sq, o);
    }
    int warp = tid >> 5, lane = tid & 31;
    if (lane == 0) { redA[warp] = s; redB[warp] = sq; }
    __syncthreads();
    float tot = 0.f, tot2 = 0.f;
#pragma unroll
    for (int i = 0; i < 8; i++) { tot += redA[i]; tot2 += redB[i]; }
    float mu   = tot  * (1.0f / DMODEL);
    float var  = tot2 * (1.0f / DMODEL) - mu * mu;
    float rstd = rsqrtf(var + 1e-5f);
    float4 wv = ((const float4*)w)[tid];
    float4 bv = ((const float4*)b)[tid];
    float4 o;
    o.x = (v.x - mu) * rstd * wv.x + bv.x;
    o.y = (v.y - mu) * rstd * wv.y + bv.y;
    o.z = (v.z - mu) * rstd * wv.z + bv.z;
    o.w = (v.w - mu) * rstd * wv.w + bv.w;
    ((float4*)(out + (size_t)row * DMODEL))[tid] = o;
}

// ---------------------------------------------------------------------------
// Classic SIMT fp32 SGEMM: 128x128 block tile, BK=8, 256 threads, 8x8/thread
// C[M,N] = A[M,K] @ B[K,N]  (all row-major), fused epilogues.
// EPI: 0 = none, 1 = bias+GELU(exact), 2 = bias+residual, 3 = residual
// ---------------------------------------------------------------------------
__device__ __forceinline__ float gelu_f(float x) {
    return 0.5f * x * (1.0f + erff(x * 0.70710678118654752f));
}

template <int EPI>
__global__ __launch_bounds__(256) void sgemm_k(
    const float* __restrict__ A, const float* __restrict__ B,
    float* __restrict__ C, int M, int N, int K,
    const float* __restrict__ bias, const float* __restrict__ resid)
{
    __shared__ float As[8][128];
    __shared__ float Bs[8][128];
    int tid = threadIdx.x;
    int bx = blockIdx.x, by = blockIdx.y;

    int aRow = tid >> 1,  aCol = (tid & 1) << 2;   // 128 x 8 A-tile loads
    int bRow = tid >> 5,  bCol = (tid & 31) << 2;  // 8 x 128 B-tile loads
    const float* Ag = A + (size_t)(by * 128 + aRow) * K + aCol;
    const float* Bg = B + (size_t)bRow * N + bx * 128 + bCol;

    int tr = (tid >> 4) << 3;   // thread row offset in tile
    int tc = (tid & 15) << 3;   // thread col offset in tile

    float acc[8][8];
#pragma unroll
    for (int i = 0; i < 8; i++)
#pragma unroll
        for (int j = 0; j < 8; j++) acc[i][j] = 0.f;

    for (int k = 0; k < K; k += 8) {
        float4 a  = *(const float4*)(Ag + k);
        float4 bb = *(const float4*)(Bg + (size_t)k * N);
        As[aCol + 0][aRow] = a.x;
        As[aCol + 1][aRow] = a.y;
        As[aCol + 2][aRow] = a.z;
        As[aCol + 3][aRow] = a.w;
        *(float4*)&Bs[bRow][bCol] = bb;
        __syncthreads();
#pragma unroll
        for (int kk = 0; kk < 8; kk++) {
            float4 a0 = *(const float4*)&As[kk][tr];
            float4 a1 = *(const float4*)&As[kk][tr + 4];
            float4 b0 = *(const float4*)&Bs[kk][tc];
            float4 b1 = *(const float4*)&Bs[kk][tc + 4];
            float ar[8] = {a0.x, a0.y, a0.z, a0.w, a1.x, a1.y, a1.z, a1.w};
            float br[8] = {b0.x, b0.y, b0.z, b0.w, b1.x, b1.y, b1.z, b1.w};
#pragma unroll
            for (int i = 0; i < 8; i++)
#pragma unroll
                for (int j = 0; j < 8; j++)
                    acc[i][j] += ar[i] * br[j];
        }
        __syncthreads();
    }

    int r0 = by * 128 + tr, c0 = bx * 128 + tc;
#pragma unroll
    for (int i = 0; i < 8; i++) {
        int r = r0 + i;
#pragma unroll
        for (int j = 0; j < 8; j++) {
            int c = c0 + j;
            float v = acc[i][j];
            if (EPI == 1)      v = gelu_f(v + bias[c]);
            else if (EPI == 2) v = v + bias[c] + resid[(size_t)r * N + c];
            else if (EPI == 3) v = v + resid[(size_t)r * N + c];
            C[(size_t)r * N + c] = v;
        }
    }
}

// ---------------------------------------------------------------------------
// Causal flash attention, fp32.
// Grid: (SEQ/32, BATCH*NHEAD). Block: 256 threads (8 warps, 4 Q-rows/warp).
// qkv layout: [B*T, 3*D] with Q at col h*64, K at 1024+h*64, V at 2048+h*64.
// KV tiles of 64 rows. Online softmax; P broadcast via shuffles.
// ---------------------------------------------------------------------------
__global__ __launch_bounds__(256) void flash_k(
    const float* __restrict__ qkv, float* __restrict__ out)
{
    __shared__ float Qs[32][64];
    __shared__ float Ks[64][65];   // +1 pad: lane-varying-row reads conflict-free
    __shared__ float Vs[64][65];

    int bh = blockIdx.y;
    int b = bh >> 4, h = bh & 15;
    int q0 = blockIdx.x * 32;
    int tid = threadIdx.x, warp = tid >> 5, lane = tid & 31;
    const float* base = qkv + (size_t)b * SEQ * 3 * DMODEL + h * HEADD;

    for (int i = tid; i < 32 * 64; i += 256) {
        int r = i >> 6, c = i & 63;
        Qs[r][c] = base[(size_t)(q0 + r) * (3 * DMODEL) + c];
    }

    float O0[4] = {0.f, 0.f, 0.f, 0.f};
    float O1[4] = {0.f, 0.f, 0.f, 0.f};
    float m[4]  = {-1e30f, -1e30f, -1e30f, -1e30f};
    float l[4]  = {0.f, 0.f, 0.f, 0.f};

    int ntiles = (q0 + 31) / 64 + 1;   // causal: only tiles with k_min <= q_max
    for (int kvb = 0; kvb < ntiles; kvb++) {
        int k0 = kvb * 64;
        __syncthreads();
        for (int i = tid; i < 64 * 64; i += 256) {
            int r = i >> 6, c = i & 63;
            const float* kvrow = base + (size_t)(k0 + r) * (3 * DMODEL) + c;
            Ks[r][c] = kvrow[DMODEL];
            Vs[r][c] = kvrow[2 * DMODEL];
        }
        __syncthreads();
        bool full = (q0 >= k0 + 63);   // tile fully unmasked for all rows

#pragma unroll
        for (int r = 0; r < 4; r++) {
            int q = q0 + (warp << 2) + r;
            const float* qrow  = Qs[(warp << 2) + r];
            const float* krow0 = Ks[lane];
            const float* krow1 = Ks[lane + 32];
            float s0 = 0.f, s1 = 0.f;
#pragma unroll
            for (int d = 0; d < 64; d++) {
                float qd = qrow[d];
                s0 += qd * krow0[d];
                s1 += qd * krow1[d];
            }
            s0 *= 0.125f; s1 *= 0.125f;   // 1/sqrt(64)
            if (!full) {
                if (k0 + lane      > q) s0 = -1e30f;
                if (k0 + lane + 32 > q) s1 = -1e30f;
            }
            float mx = fmaxf(s0, s1);
#pragma unroll
            for (int o = 16; o > 0; o >>= 1)
                mx = fmaxf(mx, __shfl_xor_sync(0xffffffffu, mx, o));
            float mnew  = fmaxf(m[r], mx);
            float alpha = __expf(m[r] - mnew);
            float p0 = __expf(s0 - mnew);
            float p1 = __expf(s1 - mnew);
            float ps = p0 + p1;
#pragma unroll
            for (int o = 16; o > 0; o >>= 1)
                ps += __shfl_xor_sync(0xffffffffu, ps, o);
            l[r] = l[r] * alpha + ps;
            m[r] = mnew;
            O0[r] *= alpha; O1[r] *= alpha;
#pragma unroll 8
            for (int j = 0; j < 32; j++) {
                float pj = __shfl_sync(0xffffffffu, p0, j);
                O0[r] += pj * Vs[j][lane];
                O1[r] += pj * Vs[j][lane + 32];
            }
#pragma unroll 8
            for (int j = 0; j < 32; j++) {
                float pj = __shfl_sync(0xffffffffu, p1, j);
                O0[r] += pj * Vs[j + 32][lane];
                O1[r] += pj * Vs[j + 32][lane + 32];
            }
        }
    }

#pragma unroll
    for (int r = 0; r < 4; r++) {
        int q = q0 + (warp << 2) + r;
        float inv = 1.0f / l[r];
        float* orow = out + (size_t)(b * SEQ + q) * DMODEL + h * HEADD;
        orow[lane]      = O0[r] * inv;
        orow[lane + 32] = O1[r] * inv;
    }
}

// ---------------------------------------------------------------------------
// Launch pipeline
// ---------------------------------------------------------------------------
extern "C" void kernel_launch(void* const* d_in, const int* in_sizes, int n_in,
                              void* d_out, int out_size)
{
    const float* x      = (const float*)d_in[0];
    const float* w_qkv  = (const float*)d_in[1];
    const float* w_proj = (const float*)d_in[2];
    const float* ln1_w  = (const float*)d_in[3];
    const float* ln1_b  = (const float*)d_in[4];
    const float* ln2_w  = (const float*)d_in[5];
    const float* ln2_b  = (const float*)d_in[6];
    const float* fc1_w  = (const float*)d_in[7];
    const float* fc1_b  = (const float*)d_in[8];
    const float* fc2_w  = (const float*)d_in[9];
    const float* fc2_b  = (const float*)d_in[10];
    float* out = (float*)d_out;

    float *ln1o, *qkv, *attn, *x1, *ln2o, *fc1o;
    cudaGetSymbolAddress((void**)&ln1o, g_ln1);
    cudaGetSymbolAddress((void**)&qkv,  g_qkv);
    cudaGetSymbolAddress((void**)&attn, g_attn);
    cudaGetSymbolAddress((void**)&x1,   g_x1);
    cudaGetSymbolAddress((void**)&ln2o, g_ln2);
    cudaGetSymbolAddress((void**)&fc1o, g_fc1);

    // 1. ln1 = LN(x)
    ln_kernel<<<MROWS, 256>>>(x, ln1_w, ln1_b, ln1o);
    // 2. qkv = ln1 @ w_qkv          [4096,3072]
    sgemm_k<0><<<dim3(3 * DMODEL / 128, MROWS / 128), 256>>>(
        ln1o, w_qkv, qkv, MROWS, 3 * DMODEL, DMODEL, nullptr, nullptr);
    // 3. attn = causal_flash(qkv)   [4096,1024]
    flash_k<<<dim3(SEQ / 32, BATCH * NHEAD), 256>>>(qkv, attn);
    // 4. x1 = x + attn @ w_proj
    sgemm_k<3><<<dim3(DMODEL / 128, MROWS / 128), 256>>>(
        attn, w_proj, x1, MROWS, DMODEL, DMODEL, nullptr, x);
    // 5. ln2 = LN(x1)
    ln_kernel<<<MROWS, 256>>>(x1, ln2_w, ln2_b, ln2o);
    // 6. fc1 = gelu(ln2 @ fc1_w + fc1_b)   [4096,4096]
    sgemm_k<1><<<dim3(DFF / 128, MROWS / 128), 256>>>(
        ln2o, fc1_w, fc1o, MROWS, DFF, DMODEL, fc1_b, nullptr);
    // 7. out = x1 + fc1 @ fc2_w + fc2_b
    sgemm_k<2><<<dim3(DMODEL / 128, MROWS / 128), 256>>>(
        fc1o, fc2_w, out, MROWS, DMODEL, DFF, fc2_b, x1);
}

// round 4
// speedup vs baseline: 1.5501x; 1.5501x over previous
#include <cuda_runtime.h>
#include <math.h>

// Problem constants
#define BATCH   2
#define SEQ     2048
#define DMODEL  1024
#define NHEAD   16
#define HEADD   64
#define DFF     4096
#define MROWS   (BATCH*SEQ)        // 4096

// Scratch buffers (device globals: no allocation allowed in kernel_launch)
__device__ float g_ln1 [MROWS*DMODEL];
__device__ float g_qkv [MROWS*3*DMODEL];
__device__ float g_attn[MROWS*DMODEL];
__device__ float g_x1  [MROWS*DMODEL];
__device__ float g_ln2 [MROWS*DMODEL];
__device__ float g_fc1 [MROWS*DFF];

// ---------------------------------------------------------------------------
// LayerNorm: one block per row, 256 threads, float4 vectorized (D=1024)
// ---------------------------------------------------------------------------
__global__ __launch_bounds__(256) void ln_kernel(
    const float* __restrict__ x, const float* __restrict__ w,
    const float* __restrict__ b, float* __restrict__ out)
{
    __shared__ float redA[8], redB[8];
    int row = blockIdx.x, tid = threadIdx.x;
    const float4* xr = (const float4*)(x + (size_t)row * DMODEL);
    float4 v = xr[tid];
    float s  = v.x + v.y + v.z + v.w;
    float sq = v.x*v.x + v.y*v.y + v.z*v.z + v.w*v.w;
#pragma unroll
    for (int o = 16; o > 0; o >>= 1) {
        s  += __shfl_xor_sync(0xffffffffu, s,  o);
        sq += __shfl_xor_sync(0xffffffffu, sq, o);
    }
    int warp = tid >> 5, lane = tid & 31;
    if (lane == 0) { redA[warp] = s; redB[warp] = sq; }
    __syncthreads();
    float tot = 0.f, tot2 = 0.f;
#pragma unroll
    for (int i = 0; i < 8; i++) { tot += redA[i]; tot2 += redB[i]; }
    float mu   = tot  * (1.0f / DMODEL);
    float var  = tot2 * (1.0f / DMODEL) - mu * mu;
    float rstd = rsqrtf(var + 1e-5f);
    float4 wv = ((const float4*)w)[tid];
    float4 bv = ((const float4*)b)[tid];
    float4 o;
    o.x = (v.x - mu) * rstd * wv.x + bv.x;
    o.y = (v.y - mu) * rstd * wv.y + bv.y;
    o.z = (v.z - mu) * rstd * wv.z + bv.z;
    o.w = (v.w - mu) * rstd * wv.w + bv.w;
    ((float4*)(out + (size_t)row * DMODEL))[tid] = o;
}

// ---------------------------------------------------------------------------
// TF32 tensor-core GEMM.
// C[M,N] = A[M,K] @ B[K,N], row-major, via mma.sync.m16n8k8.tf32.
// Block tile 128x128, BK=16, 256 threads (8 warps, 2x4), warp tile 64x32.
// A staged [m][k] stride 20 (conflict-free ldmatrix); B staged transposed
// [n][k] stride 20. Double-buffered smem + gmem->reg prefetch.
// EPI: 0 = none, 1 = bias+GELU(exact), 2 = bias+residual, 3 = residual
// ---------------------------------------------------------------------------
#define LDS_T 20     // smem row stride in floats

__device__ __forceinline__ float gelu_f(float x) {
    return 0.5f * x * (1.0f + erff(x * 0.70710678118654752f));
}

__device__ __forceinline__ unsigned f2tf32(float x) {
    unsigned u;
    asm("cvt.rna.tf32.f32 %0, %1;" : "=r"(u) : "f"(x));
    return u;
}

__device__ __forceinline__ void ldmx4(unsigned r[4], const float* p) {
    unsigned sa = (unsigned)__cvta_generic_to_shared(p);
    asm volatile("ldmatrix.sync.aligned.m8n8.x4.shared.b16 {%0,%1,%2,%3}, [%4];\n"
        : "=r"(r[0]), "=r"(r[1]), "=r"(r[2]), "=r"(r[3]) : "r"(sa));
}

__device__ __forceinline__ void mma_tf32(float d[4], const unsigned a[4],
                                         unsigned b0, unsigned b1) {
    asm volatile(
        "mma.sync.aligned.m16n8k8.row.col.f32.tf32.tf32.f32 "
        "{%0,%1,%2,%3}, {%4,%5,%6,%7}, {%8,%9}, {%0,%1,%2,%3};\n"
        : "+f"(d[0]), "+f"(d[1]), "+f"(d[2]), "+f"(d[3])
        : "r"(a[0]), "r"(a[1]), "r"(a[2]), "r"(a[3]), "r"(b0), "r"(b1));
}

template <int EPI>
__global__ __launch_bounds__(256, 2) void mma_gemm(
    const float* __restrict__ A, const float* __restrict__ B,
    float* __restrict__ C, int M, int N, int K,
    const float* __restrict__ bias, const float* __restrict__ resid)
{
    __shared__ __align__(16) float As[2][128 * LDS_T];
    __shared__ __align__(16) float Bs[2][128 * LDS_T];

    const int tid  = threadIdx.x;
    const int lane = tid & 31;
    const int warp = tid >> 5;
    const int bx = blockIdx.x, by = blockIdx.y;
    const int wm = (warp >> 2) * 64;   // warp row offset in tile
    const int wn = (warp & 3) * 32;    // warp col offset in tile

    float acc[4][4][4];
#pragma unroll
    for (int i = 0; i < 4; i++)
#pragma unroll
        for (int j = 0; j < 4; j++)
#pragma unroll
            for (int t = 0; t < 4; t++) acc[i][j][t] = 0.f;

    // A staging: thread loads 8 floats: row = tid>>1, k = (tid&1)*8 .. +7
    const int arow = tid >> 1, akb = (tid & 1) << 3;
    const float* Ag = A + (size_t)(by * 128 + arow) * K + akb;
    // B staging: thread loads 8 floats: n = tid&127, k = (tid>>7) + 2j
    const int bn = tid & 127, bk0 = tid >> 7;
    const float* Bg = B + (size_t)bx * 128 + bn;

    float aReg[8], bReg[8];

    auto LOAD = [&](int kt) {
        float4 v0 = *(const float4*)(Ag + kt * 16);
        float4 v1 = *(const float4*)(Ag + kt * 16 + 4);
        aReg[0]=v0.x; aReg[1]=v0.y; aReg[2]=v0.z; aReg[3]=v0.w;
        aReg[4]=v1.x; aReg[5]=v1.y; aReg[6]=v1.z; aReg[7]=v1.w;
#pragma unroll
        for (int j = 0; j < 8; j++)
            bReg[j] = Bg[(size_t)(kt * 16 + bk0 + 2 * j) * N];
    };

    auto STORE = [&](int buf) {
        float* as = &As[buf][arow * LDS_T + akb];
#pragma unroll
        for (int i = 0; i < 8; i++)
            as[i] = __uint_as_float(f2tf32(aReg[i]));
        float* bs = &Bs[buf][bn * LDS_T + bk0];
#pragma unroll
        for (int j = 0; j < 8; j++)
            bs[2 * j] = __uint_as_float(f2tf32(bReg[j]));
    };

    auto COMPUTE = [&](int buf) {
        const float* as = As[buf];
        const float* bs = Bs[buf];
#pragma unroll
        for (int k8 = 0; k8 < 2; k8++) {
            unsigned af[4][4], bf[2][4];
            int koff = k8 * 8 + (lane >> 4) * 4;
#pragma unroll
            for (int mt = 0; mt < 4; mt++)
                ldmx4(af[mt], as + (wm + mt * 16 + (lane & 15)) * LDS_T + koff);
#pragma unroll
            for (int p = 0; p < 2; p++)
                ldmx4(bf[p], bs + (wn + p * 16 + (lane & 15)) * LDS_T + koff);
#pragma unroll
            for (int mt = 0; mt < 4; mt++)
#pragma unroll
                for (int nt = 0; nt < 4; nt++)
                    mma_tf32(acc[mt][nt], af[mt],
                             bf[nt >> 1][nt & 1], bf[nt >> 1][(nt & 1) + 2]);
        }
    };

    const int KT = K >> 4;
    LOAD(0);
    STORE(0);
    __syncthreads();
    for (int kt = 0; kt < KT; kt++) {
        int cur = kt & 1;
        if (kt + 1 < KT) LOAD(kt + 1);
        COMPUTE(cur);
        if (kt + 1 < KT) STORE(cur ^ 1);
        __syncthreads();
    }

    // Epilogue: c0,c1 at (row, col..col+1), c2,c3 at (row+8, same cols)
#pragma unroll
    for (int mt = 0; mt < 4; mt++) {
#pragma unroll
        for (int nt = 0; nt < 4; nt++) {
            int r = by * 128 + wm + mt * 16 + (lane >> 2);
            int c = bx * 128 + wn + nt * 8 + (lane & 3) * 2;
#pragma unroll
            for (int half = 0; half < 2; half++) {
                int rr = r + half * 8;
                float v0 = acc[mt][nt][half * 2 + 0];
                float v1 = acc[mt][nt][half * 2 + 1];
                if (EPI == 1) {
                    v0 = gelu_f(v0 + bias[c]);
                    v1 = gelu_f(v1 + bias[c + 1]);
                } else if (EPI == 2) {
                    v0 += bias[c]     + resid[(size_t)rr * N + c];
                    v1 += bias[c + 1] + resid[(size_t)rr * N + c + 1];
                } else if (EPI == 3) {
                    v0 += resid[(size_t)rr * N + c];
                    v1 += resid[(size_t)rr * N + c + 1];
                }
                float2 o = {v0, v1};
                *(float2*)&C[(size_t)rr * N + c] = o;
            }
        }
    }
}

// ---------------------------------------------------------------------------
// Causal flash attention, fp32 (unchanged this round).
// ---------------------------------------------------------------------------
__global__ __launch_bounds__(256) void flash_k(
    const float* __restrict__ qkv, float* __restrict__ out)
{
    __shared__ float Qs[32][64];
    __shared__ float Ks[64][65];
    __shared__ float Vs[64][65];

    int bh = blockIdx.y;
    int b = bh >> 4, h = bh & 15;
    int q0 = blockIdx.x * 32;
    int tid = threadIdx.x, warp = tid >> 5, lane = tid & 31;
    const float* base = qkv + (size_t)b * SEQ * 3 * DMODEL + h * HEADD;

    for (int i = tid; i < 32 * 64; i += 256) {
        int r = i >> 6, c = i & 63;
        Qs[r][c] = base[(size_t)(q0 + r) * (3 * DMODEL) + c];
    }

    float O0[4] = {0.f, 0.f, 0.f, 0.f};
    float O1[4] = {0.f, 0.f, 0.f, 0.f};
    float m[4]  = {-1e30f, -1e30f, -1e30f, -1e30f};
    float l[4]  = {0.f, 0.f, 0.f, 0.f};

    int ntiles = (q0 + 31) / 64 + 1;
    for (int kvb = 0; kvb < ntiles; kvb++) {
        int k0 = kvb * 64;
        __syncthreads();
        for (int i = tid; i < 64 * 64; i += 256) {
            int r = i >> 6, c = i & 63;
            const float* kvrow = base + (size_t)(k0 + r) * (3 * DMODEL) + c;
            Ks[r][c] = kvrow[DMODEL];
            Vs[r][c] = kvrow[2 * DMODEL];
        }
        __syncthreads();
        bool full = (q0 >= k0 + 63);

#pragma unroll
        for (int r = 0; r < 4; r++) {
            int q = q0 + (warp << 2) + r;
            const float* qrow  = Qs[(warp << 2) + r];
            const float* krow0 = Ks[lane];
            const float* krow1 = Ks[lane + 32];
            float s0 = 0.f, s1 = 0.f;
#pragma unroll
            for (int d = 0; d < 64; d++) {
                float qd = qrow[d];
                s0 += qd * krow0[d];
                s1 += qd * krow1[d];
            }
            s0 *= 0.125f; s1 *= 0.125f;
            if (!full) {
                if (k0 + lane      > q) s0 = -1e30f;
                if (k0 + lane + 32 > q) s1 = -1e30f;
            }
            float mx = fmaxf(s0, s1);
#pragma unroll
            for (int o = 16; o > 0; o >>= 1)
                mx = fmaxf(mx, __shfl_xor_sync(0xffffffffu, mx, o));
            float mnew  = fmaxf(m[r], mx);
            float alpha = __expf(m[r] - mnew);
            float p0 = __expf(s0 - mnew);
            float p1 = __expf(s1 - mnew);
            float ps = p0 + p1;
#pragma unroll
            for (int o = 16; o > 0; o >>= 1)
                ps += __shfl_xor_sync(0xffffffffu, ps, o);
            l[r] = l[r] * alpha + ps;
            m[r] = mnew;
            O0[r] *= alpha; O1[r] *= alpha;
#pragma unroll 8
            for (int j = 0; j < 32; j++) {
                float pj = __shfl_sync(0xffffffffu, p0, j);
                O0[r] += pj * Vs[j][lane];
                O1[r] += pj * Vs[j][lane + 32];
            }
#pragma unroll 8
            for (int j = 0; j < 32; j++) {
                float pj = __shfl_sync(0xffffffffu, p1, j);
                O0[r] += pj * Vs[j + 32][lane];
                O1[r] += pj * Vs[j + 32][lane + 32];
            }
        }
    }

#pragma unroll
    for (int r = 0; r < 4; r++) {
        int q = q0 + (warp << 2) + r;
        float inv = 1.0f / l[r];
        float* orow = out + (size_t)(b * SEQ + q) * DMODEL + h * HEADD;
        orow[lane]      = O0[r] * inv;
        orow[lane + 32] = O1[r] * inv;
    }
}

// ---------------------------------------------------------------------------
// Launch pipeline
// ---------------------------------------------------------------------------
extern "C" void kernel_launch(void* const* d_in, const int* in_sizes, int n_in,
                              void* d_out, int out_size)
{
    const float* x      = (const float*)d_in[0];
    const float* w_qkv  = (const float*)d_in[1];
    const float* w_proj = (const float*)d_in[2];
    const float* ln1_w  = (const float*)d_in[3];
    const float* ln1_b  = (const float*)d_in[4];
    const float* ln2_w  = (const float*)d_in[5];
    const float* ln2_b  = (const float*)d_in[6];
    const float* fc1_w  = (const float*)d_in[7];
    const float* fc1_b  = (const float*)d_in[8];
    const float* fc2_w  = (const float*)d_in[9];
    const float* fc2_b  = (const float*)d_in[10];
    float* out = (float*)d_out;

    float *ln1o, *qkv, *attn, *x1, *ln2o, *fc1o;
    cudaGetSymbolAddress((void**)&ln1o, g_ln1);
    cudaGetSymbolAddress((void**)&qkv,  g_qkv);
    cudaGetSymbolAddress((void**)&attn, g_attn);
    cudaGetSymbolAddress((void**)&x1,   g_x1);
    cudaGetSymbolAddress((void**)&ln2o, g_ln2);
    cudaGetSymbolAddress((void**)&fc1o, g_fc1);

    // 1. ln1 = LN(x)
    ln_kernel<<<MROWS, 256>>>(x, ln1_w, ln1_b, ln1o);
    // 2. qkv = ln1 @ w_qkv          [4096,3072]
    mma_gemm<0><<<dim3(3 * DMODEL / 128, MROWS / 128), 256>>>(
        ln1o, w_qkv, qkv, MROWS, 3 * DMODEL, DMODEL, nullptr, nullptr);
    // 3. attn = causal_flash(qkv)   [4096,1024]
    flash_k<<<dim3(SEQ / 32, BATCH * NHEAD), 256>>>(qkv, attn);
    // 4. x1 = x + attn @ w_proj
    mma_gemm<3><<<dim3(DMODEL / 128, MROWS / 128), 256>>>(
        attn, w_proj, x1, MROWS, DMODEL, DMODEL, nullptr, x);
    // 5. ln2 = LN(x1)
    ln_kernel<<<MROWS, 256>>>(x1, ln2_w, ln2_b, ln2o);
    // 6. fc1 = gelu(ln2 @ fc1_w + fc1_b)   [4096,4096]
    mma_gemm<1><<<dim3(DFF / 128, MROWS / 128), 256>>>(
        ln2o, fc1_w, fc1o, MROWS, DFF, DMODEL, fc1_b, nullptr);
    // 7. out = x1 + fc1 @ fc2_w + fc2_b
    mma_gemm<2><<<dim3(DMODEL / 128, MROWS / 128), 256>>>(
        fc1o, fc2_w, out, MROWS, DMODEL, DFF, fc2_b, x1);
}

// round 7
// speedup vs baseline: 3.6552x; 2.3580x over previous
#include <cuda_runtime.h>
#include <math.h>

// Problem constants
#define BATCH   2
#define SEQ     2048
#define DMODEL  1024
#define NHEAD   16
#define HEADD   64
#define DFF     4096
#define MROWS   (BATCH*SEQ)        // 4096

// Scratch buffers (device globals: no allocation allowed in kernel_launch)
__device__ float g_ln1 [MROWS*DMODEL];
__device__ float g_qkv [MROWS*3*DMODEL];
__device__ float g_attn[MROWS*DMODEL];
__device__ float g_x1  [MROWS*DMODEL];
__device__ float g_ln2 [MROWS*DMODEL];
__device__ float g_fc1 [MROWS*DFF];

// ---------------------------------------------------------------------------
// LayerNorm: one block per row, 256 threads, float4 vectorized (D=1024)
// ---------------------------------------------------------------------------
__global__ __launch_bounds__(256) void ln_kernel(
    const float* __restrict__ x, const float* __restrict__ w,
    const float* __restrict__ b, float* __restrict__ out)
{
    __shared__ float redA[8], redB[8];
    int row = blockIdx.x, tid = threadIdx.x;
    const float4* xr = (const float4*)(x + (size_t)row * DMODEL);
    float4 v = xr[tid];
    float s  = v.x + v.y + v.z + v.w;
    float sq = v.x*v.x + v.y*v.y + v.z*v.z + v.w*v.w;
#pragma unroll
    for (int o = 16; o > 0; o >>= 1) {
        s  += __shfl_xor_sync(0xffffffffu, s,  o);
        sq += __shfl_xor_sync(0xffffffffu, sq, o);
    }
    int warp = tid >> 5, lane = tid & 31;
    if (lane == 0) { redA[warp] = s; redB[warp] = sq; }
    __syncthreads();
    float tot = 0.f, tot2 = 0.f;
#pragma unroll
    for (int i = 0; i < 8; i++) { tot += redA[i]; tot2 += redB[i]; }
    float mu   = tot  * (1.0f / DMODEL);
    float var  = tot2 * (1.0f / DMODEL) - mu * mu;
    float rstd = rsqrtf(var + 1e-5f);
    float4 wv = ((const float4*)w)[tid];
    float4 bv = ((const float4*)b)[tid];
    float4 o;
    o.x = (v.x - mu) * rstd * wv.x + bv.x;
    o.y = (v.y - mu) * rstd * wv.y + bv.y;
    o.z = (v.z - mu) * rstd * wv.z + bv.z;
    o.w = (v.w - mu) * rstd * wv.w + bv.w;
    ((float4*)(out + (size_t)row * DMODEL))[tid] = o;
}

// ---------------------------------------------------------------------------
// Shared MMA helpers (tf32 m16n8k8)
// ---------------------------------------------------------------------------
__device__ __forceinline__ float gelu_f(float x) {
    return 0.5f * x * (1.0f + erff(x * 0.70710678118654752f));
}

__device__ __forceinline__ unsigned f2tf32(float x) {
    unsigned u;
    asm("cvt.rna.tf32.f32 %0, %1;" : "=r"(u) : "f"(x));
    return u;
}

__device__ __forceinline__ void ldmx4(unsigned r[4], const float* p) {
    unsigned sa = (unsigned)__cvta_generic_to_shared(p);
    asm volatile("ldmatrix.sync.aligned.m8n8.x4.shared.b16 {%0,%1,%2,%3}, [%4];\n"
        : "=r"(r[0]), "=r"(r[1]), "=r"(r[2]), "=r"(r[3]) : "r"(sa));
}

__device__ __forceinline__ void mma_tf32(float d[4], const unsigned a[4],
                                         unsigned b0, unsigned b1) {
    asm volatile(
        "mma.sync.aligned.m16n8k8.row.col.f32.tf32.tf32.f32 "
        "{%0,%1,%2,%3}, {%4,%5,%6,%7}, {%8,%9}, {%0,%1,%2,%3};\n"
        : "+f"(d[0]), "+f"(d[1]), "+f"(d[2]), "+f"(d[3])
        : "r"(a[0]), "r"(a[1]), "r"(a[2]), "r"(a[3]), "r"(b0), "r"(b1));
}

// ---------------------------------------------------------------------------
// TF32 tensor-core GEMM (unchanged from R4).
// ---------------------------------------------------------------------------
#define LDS_T 20     // smem row stride in floats

template <int EPI>
__global__ __launch_bounds__(256, 2) void mma_gemm(
    const float* __restrict__ A, const float* __restrict__ B,
    float* __restrict__ C, int M, int N, int K,
    const float* __restrict__ bias, const float* __restrict__ resid)
{
    __shared__ __align__(16) float As[2][128 * LDS_T];
    __shared__ __align__(16) float Bs[2][128 * LDS_T];

    const int tid  = threadIdx.x;
    const int lane = tid & 31;
    const int warp = tid >> 5;
    const int bx = blockIdx.x, by = blockIdx.y;
    const int wm = (warp >> 2) * 64;
    const int wn = (warp & 3) * 32;

    float acc[4][4][4];
#pragma unroll
    for (int i = 0; i < 4; i++)
#pragma unroll
        for (int j = 0; j < 4; j++)
#pragma unroll
            for (int t = 0; t < 4; t++) acc[i][j][t] = 0.f;

    const int arow = tid >> 1, akb = (tid & 1) << 3;
    const float* Ag = A + (size_t)(by * 128 + arow) * K + akb;
    const int bn = tid & 127, bk0 = tid >> 7;
    const float* Bg = B + (size_t)bx * 128 + bn;

    float aReg[8], bReg[8];

    auto LOAD = [&](int kt) {
        float4 v0 = *(const float4*)(Ag + kt * 16);
        float4 v1 = *(const float4*)(Ag + kt * 16 + 4);
        aReg[0]=v0.x; aReg[1]=v0.y; aReg[2]=v0.z; aReg[3]=v0.w;
        aReg[4]=v1.x; aReg[5]=v1.y; aReg[6]=v1.z; aReg[7]=v1.w;
#pragma unroll
        for (int j = 0; j < 8; j++)
            bReg[j] = Bg[(size_t)(kt * 16 + bk0 + 2 * j) * N];
    };

    auto STORE = [&](int buf) {
        float* as = &As[buf][arow * LDS_T + akb];
#pragma unroll
        for (int i = 0; i < 8; i++)
            as[i] = __uint_as_float(f2tf32(aReg[i]));
        float* bs = &Bs[buf][bn * LDS_T + bk0];
#pragma unroll
        for (int j = 0; j < 8; j++)
            bs[2 * j] = __uint_as_float(f2tf32(bReg[j]));
    };

    auto COMPUTE = [&](int buf) {
        const float* as = As[buf];
        const float* bs = Bs[buf];
#pragma unroll
        for (int k8 = 0; k8 < 2; k8++) {
            unsigned af[4][4], bf[2][4];
            int koff = k8 * 8 + (lane >> 4) * 4;
#pragma unroll
            for (int mt = 0; mt < 4; mt++)
                ldmx4(af[mt], as + (wm + mt * 16 + (lane & 15)) * LDS_T + koff);
#pragma unroll
            for (int p = 0; p < 2; p++)
                ldmx4(bf[p], bs + (wn + p * 16 + (lane & 15)) * LDS_T + koff);
#pragma unroll
            for (int mt = 0; mt < 4; mt++)
#pragma unroll
                for (int nt = 0; nt < 4; nt++)
                    mma_tf32(acc[mt][nt], af[mt],
                             bf[nt >> 1][nt & 1], bf[nt >> 1][(nt & 1) + 2]);
        }
    };

    const int KT = K >> 4;
    LOAD(0);
    STORE(0);
    __syncthreads();
    for (int kt = 0; kt < KT; kt++) {
        int cur = kt & 1;
        if (kt + 1 < KT) LOAD(kt + 1);
        COMPUTE(cur);
        if (kt + 1 < KT) STORE(cur ^ 1);
        __syncthreads();
    }

#pragma unroll
    for (int mt = 0; mt < 4; mt++) {
#pragma unroll
        for (int nt = 0; nt < 4; nt++) {
            int r = by * 128 + wm + mt * 16 + (lane >> 2);
            int c = bx * 128 + wn + nt * 8 + (lane & 3) * 2;
#pragma unroll
            for (int half = 0; half < 2; half++) {
                int rr = r + half * 8;
                float v0 = acc[mt][nt][half * 2 + 0];
                float v1 = acc[mt][nt][half * 2 + 1];
                if (EPI == 1) {
                    v0 = gelu_f(v0 + bias[c]);
                    v1 = gelu_f(v1 + bias[c + 1]);
                } else if (EPI == 2) {
                    v0 += bias[c]     + resid[(size_t)rr * N + c];
                    v1 += bias[c + 1] + resid[(size_t)rr * N + c + 1];
                } else if (EPI == 3) {
                    v0 += resid[(size_t)rr * N + c];
                    v1 += resid[(size_t)rr * N + c + 1];
                }
                float2 o = {v0, v1};
                *(float2*)&C[(size_t)rr * N + c] = o;
            }
        }
    }
}

// ---------------------------------------------------------------------------
// Tensor-core causal flash attention (tf32 m16n8k8).
// Grid: (SEQ/64, BATCH*NHEAD). Block: 128 threads = 4 warps, 16 Q-rows/warp.
// Dynamic smem: Qs[64][68], Ks[64][68], Vt[64][68] (V transposed: rows=d),
// Ps[4][16][68] (warp-private P tile). Stride 68 => conflict-free ldmatrix.
// qkv layout: [B*T, 3*D], Q at h*64, K at 1024+h*64, V at 2048+h*64.
// ---------------------------------------------------------------------------
#define FST 68
#define FSM_Q  0
#define FSM_K  (64 * FST)
#define FSM_V  (2 * 64 * FST)
#define FSM_P  (3 * 64 * FST)
#define FSM_TOT ((3 * 64 + 4 * 16) * FST * 4)   // bytes = 69632

__global__ __launch_bounds__(128) void flash_mma(
    const float* __restrict__ qkv, float* __restrict__ out)
{
    extern __shared__ __align__(16) float fsm[];
    float* Qs = fsm + FSM_Q;
    float* Ks = fsm + FSM_K;
    float* Vt = fsm + FSM_V;

    const int bh = blockIdx.y;
    const int b = bh >> 4, h = bh & 15;
    const int q0 = blockIdx.x * 64;
    const int tid = threadIdx.x, warp = tid >> 5, lane = tid & 31;
    float* Ps = fsm + FSM_P + warp * 16 * FST;
    const float* base = qkv + (size_t)b * SEQ * 3 * DMODEL + h * HEADD;

    // Stage Q (scaled by 1/sqrt(64), tf32). 64 rows x 16 float4.
    for (int i = tid; i < 64 * 16; i += 128) {
        int r = i >> 4, c = (i & 15) << 2;
        float4 v = *(const float4*)(base + (size_t)(q0 + r) * (3 * DMODEL) + c);
        float* d = &Qs[r * FST + c];
        d[0] = __uint_as_float(f2tf32(v.x * 0.125f));
        d[1] = __uint_as_float(f2tf32(v.y * 0.125f));
        d[2] = __uint_as_float(f2tf32(v.z * 0.125f));
        d[3] = __uint_as_float(f2tf32(v.w * 0.125f));
    }

    // Accumulators: O[8 n-tiles][4], rows (lane>>2, lane>>2+8), softmax state.
    float O[8][4];
#pragma unroll
    for (int i = 0; i < 8; i++)
#pragma unroll
        for (int t = 0; t < 4; t++) O[i][t] = 0.f;
    float m[2] = {-1e30f, -1e30f};
    float l[2] = {0.f, 0.f};

    const int ntiles = q0 / 64 + 1;
    for (int kvb = 0; kvb < ntiles; kvb++) {
        const int k0 = kvb * 64;
        __syncthreads();   // protect Ks/Vt from previous iteration's readers
        for (int i = tid; i < 64 * 16; i += 128) {
            int r = i >> 4, c = (i & 15) << 2;
            const float* kr = base + (size_t)(k0 + r) * (3 * DMODEL) + DMODEL + c;
            float4 kv4 = *(const float4*)kr;
            float* kd = &Ks[r * FST + c];
            kd[0] = __uint_as_float(f2tf32(kv4.x));
            kd[1] = __uint_as_float(f2tf32(kv4.y));
            kd[2] = __uint_as_float(f2tf32(kv4.z));
            kd[3] = __uint_as_float(f2tf32(kv4.w));
            float4 vv = *(const float4*)(kr + DMODEL);
            Vt[(c + 0) * FST + r] = __uint_as_float(f2tf32(vv.x));
            Vt[(c + 1) * FST + r] = __uint_as_float(f2tf32(vv.y));
            Vt[(c + 2) * FST + r] = __uint_as_float(f2tf32(vv.z));
            Vt[(c + 3) * FST + r] = __uint_as_float(f2tf32(vv.w));
        }
        __syncthreads();

        // ---- S = Q @ K^T  (warp's m16 x n64, k=64) ----
        float S[8][4];
#pragma unroll
        for (int i = 0; i < 8; i++)
#pragma unroll
            for (int t = 0; t < 4; t++) S[i][t] = 0.f;
#pragma unroll
        for (int k8 = 0; k8 < 8; k8++) {
            unsigned af[4], bf[4];
            int koff = k8 * 8 + (lane >> 4) * 4;
            ldmx4(af, Qs + (warp * 16 + (lane & 15)) * FST + koff);
#pragma unroll
            for (int p = 0; p < 4; p++) {
                ldmx4(bf, Ks + (p * 16 + (lane & 15)) * FST + koff);
                mma_tf32(S[2 * p],     af, bf[0], bf[2]);
                mma_tf32(S[2 * p + 1], af, bf[1], bf[3]);
            }
        }

        // ---- online softmax (C layout: 2 rows x 16 cols per thread) ----
        const bool diag = (k0 == q0);
        const int cb = 2 * (lane & 3);
#pragma unroll
        for (int half = 0; half < 2; half++) {
            int qrow = q0 + warp * 16 + (lane >> 2) + half * 8;
            if (diag) {
#pragma unroll
                for (int nt = 0; nt < 8; nt++) {
#pragma unroll
                    for (int j = 0; j < 2; j++) {
                        if (k0 + nt * 8 + cb + j > qrow)
                            S[nt][half * 2 + j] = -1e30f;
                    }
                }
            }
            float mx = -1e30f;
#pragma unroll
            for (int nt = 0; nt < 8; nt++)
                mx = fmaxf(mx, fmaxf(S[nt][half * 2], S[nt][half * 2 + 1]));
            mx = fmaxf(mx, __shfl_xor_sync(0xffffffffu, mx, 1));
            mx = fmaxf(mx, __shfl_xor_sync(0xffffffffu, mx, 2));
            float mnew  = fmaxf(m[half], mx);
            float alpha = __expf(m[half] - mnew);
            m[half] = mnew;
            float ps = 0.f;
#pragma unroll
            for (int nt = 0; nt < 8; nt++) {
#pragma unroll
                for (int j = 0; j < 2; j++) {
                    float p = __expf(S[nt][half * 2 + j] - mnew);
                    S[nt][half * 2 + j] = p;
                    ps += p;
                }
            }
            ps += __shfl_xor_sync(0xffffffffu, ps, 1);
            ps += __shfl_xor_sync(0xffffffffu, ps, 2);
            l[half] = l[half] * alpha + ps;
#pragma unroll
            for (int nt = 0; nt < 8; nt++) {
                O[nt][half * 2]     *= alpha;
                O[nt][half * 2 + 1] *= alpha;
            }
        }

        // ---- store P (tf32) to warp-private smem tile ----
#pragma unroll
        for (int half = 0; half < 2; half++) {
            int r = (lane >> 2) + half * 8;
#pragma unroll
            for (int nt = 0; nt < 8; nt++) {
                Ps[r * FST + nt * 8 + cb]     = __uint_as_float(f2tf32(S[nt][half * 2]));
                Ps[r * FST + nt * 8 + cb + 1] = __uint_as_float(f2tf32(S[nt][half * 2 + 1]));
            }
        }
        __syncwarp();

        // ---- O += P @ V  (A = Ps m16 k64, B = Vt rows=d n64) ----
#pragma unroll
        for (int k8 = 0; k8 < 8; k8++) {
            unsigned af[4], bf[4];
            int koff = k8 * 8 + (lane >> 4) * 4;
            ldmx4(af, Ps + (lane & 15) * FST + koff);
#pragma unroll
            for (int p = 0; p < 4; p++) {
                ldmx4(bf, Vt + (p * 16 + (lane & 15)) * FST + koff);
                mma_tf32(O[2 * p],     af, bf[0], bf[2]);
                mma_tf32(O[2 * p + 1], af, bf[1], bf[3]);
            }
        }
    }

    // ---- normalize and write out ----
#pragma unroll
    for (int half = 0; half < 2; half++) {
        float inv = 1.0f / l[half];
        int q = q0 + warp * 16 + (lane >> 2) + half * 8;
        float* orow = out + (size_t)(b * SEQ + q) * DMODEL + h * HEADD;
#pragma unroll
        for (int nt = 0; nt < 8; nt++) {
            float2 o = {O[nt][half * 2] * inv, O[nt][half * 2 + 1] * inv};
            *(float2*)&orow[nt * 8 + 2 * (lane & 3)] = o;
        }
    }
}

// ---------------------------------------------------------------------------
// Launch pipeline
// ---------------------------------------------------------------------------
extern "C" void kernel_launch(void* const* d_in, const int* in_sizes, int n_in,
                              void* d_out, int out_size)
{
    const float* x      = (const float*)d_in[0];
    const float* w_qkv  = (const float*)d_in[1];
    const float* w_proj = (const float*)d_in[2];
    const float* ln1_w  = (const float*)d_in[3];
    const float* ln1_b  = (const float*)d_in[4];
    const float* ln2_w  = (const float*)d_in[5];
    const float* ln2_b  = (const float*)d_in[6];
    const float* fc1_w  = (const float*)d_in[7];
    const float* fc1_b  = (const float*)d_in[8];
    const float* fc2_w  = (const float*)d_in[9];
    const float* fc2_b  = (const float*)d_in[10];
    float* out = (float*)d_out;

    float *ln1o, *qkv, *attn, *x1, *ln2o, *fc1o;
    cudaGetSymbolAddress((void**)&ln1o, g_ln1);
    cudaGetSymbolAddress((void**)&qkv,  g_qkv);
    cudaGetSymbolAddress((void**)&attn, g_attn);
    cudaGetSymbolAddress((void**)&x1,   g_x1);
    cudaGetSymbolAddress((void**)&ln2o, g_ln2);
    cudaGetSymbolAddress((void**)&fc1o, g_fc1);

    static bool attr_set = false;
    if (!attr_set) {
        cudaFuncSetAttribute(flash_mma,
            cudaFuncAttributeMaxDynamicSharedMemorySize, FSM_TOT);
        attr_set = true;
    }

    // 1. ln1 = LN(x)
    ln_kernel<<<MROWS, 256>>>(x, ln1_w, ln1_b, ln1o);
    // 2. qkv = ln1 @ w_qkv          [4096,3072]
    mma_gemm<0><<<dim3(3 * DMODEL / 128, MROWS / 128), 256>>>(
        ln1o, w_qkv, qkv, MROWS, 3 * DMODEL, DMODEL, nullptr, nullptr);
    // 3. attn = causal_flash(qkv)   [4096,1024]
    flash_mma<<<dim3(SEQ / 64, BATCH * NHEAD), 128, FSM_TOT>>>(qkv, attn);
    // 4. x1 = x + attn @ w_proj
    mma_gemm<3><<<dim3(DMODEL / 128, MROWS / 128), 256>>>(
        attn, w_proj, x1, MROWS, DMODEL, DMODEL, nullptr, x);
    // 5. ln2 = LN(x1)
    ln_kernel<<<MROWS, 256>>>(x1, ln2_w, ln2_b, ln2o);
    // 6. fc1 = gelu(ln2 @ fc1_w + fc1_b)   [4096,4096]
    mma_gemm<1><<<dim3(DFF / 128, MROWS / 128), 256>>>(
        ln2o, fc1_w, fc1o, MROWS, DFF, DMODEL, fc1_b, nullptr);
    // 7. out = x1 + fc1 @ fc2_w + fc2_b
    mma_gemm<2><<<dim3(DMODEL / 128, MROWS / 128), 256>>>(
        fc1o, fc2_w, out, MROWS, DMODEL, DFF, fc2_b, x1);
}

// round 8
// speedup vs baseline: 4.9777x; 1.3618x over previous
#include <cuda_runtime.h>
#include <math.h>

// Problem constants
#define BATCH   2
#define SEQ     2048
#define DMODEL  1024
#define NHEAD   16
#define HEADD   64
#define DFF     4096
#define MROWS   (BATCH*SEQ)        // 4096

// Scratch buffers (device globals: no allocation allowed in kernel_launch)
__device__ float g_ln1 [MROWS*DMODEL];
__device__ float g_qkv [MROWS*3*DMODEL];
__device__ float g_attn[MROWS*DMODEL];
__device__ float g_x1  [MROWS*DMODEL];
__device__ float g_ln2 [MROWS*DMODEL];
__device__ float g_fc1 [MROWS*DFF];

// ---------------------------------------------------------------------------
// LayerNorm: one block per row, 256 threads, float4 vectorized (D=1024)
// ---------------------------------------------------------------------------
__global__ __launch_bounds__(256) void ln_kernel(
    const float* __restrict__ x, const float* __restrict__ w,
    const float* __restrict__ b, float* __restrict__ out)
{
    __shared__ float redA[8], redB[8];
    int row = blockIdx.x, tid = threadIdx.x;
    const float4* xr = (const float4*)(x + (size_t)row * DMODEL);
    float4 v = xr[tid];
    float s  = v.x + v.y + v.z + v.w;
    float sq = v.x*v.x + v.y*v.y + v.z*v.z + v.w*v.w;
#pragma unroll
    for (int o = 16; o > 0; o >>= 1) {
        s  += __shfl_xor_sync(0xffffffffu, s,  o);
        sq += __shfl_xor_sync(0xffffffffu, sq, o);
    }
    int warp = tid >> 5, lane = tid & 31;
    if (lane == 0) { redA[warp] = s; redB[warp] = sq; }
    __syncthreads();
    float tot = 0.f, tot2 = 0.f;
#pragma unroll
    for (int i = 0; i < 8; i++) { tot += redA[i]; tot2 += redB[i]; }
    float mu   = tot  * (1.0f / DMODEL);
    float var  = tot2 * (1.0f / DMODEL) - mu * mu;
    float rstd = rsqrtf(var + 1e-5f);
    float4 wv = ((const float4*)w)[tid];
    float4 bv = ((const float4*)b)[tid];
    float4 o;
    o.x = (v.x - mu) * rstd * wv.x + bv.x;
    o.y = (v.y - mu) * rstd * wv.y + bv.y;
    o.z = (v.z - mu) * rstd * wv.z + bv.z;
    o.w = (v.w - mu) * rstd * wv.w + bv.w;
    ((float4*)(out + (size_t)row * DMODEL))[tid] = o;
}

// ---------------------------------------------------------------------------
// Shared MMA helpers (tf32 m16n8k8)
// ---------------------------------------------------------------------------
__device__ __forceinline__ float gelu_f(float x) {
    return 0.5f * x * (1.0f + erff(x * 0.70710678118654752f));
}

__device__ __forceinline__ unsigned f2tf32(float x) {
    unsigned u;
    asm("cvt.rna.tf32.f32 %0, %1;" : "=r"(u) : "f"(x));
    return u;
}

__device__ __forceinline__ void ldmx4(unsigned r[4], const float* p) {
    unsigned sa = (unsigned)__cvta_generic_to_shared(p);
    asm volatile("ldmatrix.sync.aligned.m8n8.x4.shared.b16 {%0,%1,%2,%3}, [%4];\n"
        : "=r"(r[0]), "=r"(r[1]), "=r"(r[2]), "=r"(r[3]) : "r"(sa));
}

__device__ __forceinline__ void mma_tf32(float d[4], const unsigned a[4],
                                         unsigned b0, unsigned b1) {
    asm volatile(
        "mma.sync.aligned.m16n8k8.row.col.f32.tf32.tf32.f32 "
        "{%0,%1,%2,%3}, {%4,%5,%6,%7}, {%8,%9}, {%0,%1,%2,%3};\n"
        : "+f"(d[0]), "+f"(d[1]), "+f"(d[2]), "+f"(d[3])
        : "r"(a[0]), "r"(a[1]), "r"(a[2]), "r"(a[3]), "r"(b0), "r"(b1));
}

__device__ __forceinline__ void cp16(unsigned s, const void* g) {
    asm volatile("cp.async.cg.shared.global [%0], [%1], 16;\n" :: "r"(s), "l"(g));
}
__device__ __forceinline__ void cp_commit() {
    asm volatile("cp.async.commit_group;\n" ::: "memory");
}
__device__ __forceinline__ void cp_wait1() {
    asm volatile("cp.async.wait_group 1;\n" ::: "memory");
}

// ---------------------------------------------------------------------------
// TF32 tensor-core GEMM, cp.async 3-stage pipeline.
// C[M,N] = A[M,K] @ B[K,N], row-major. Block tile 128x128, BK=16,
// 128 threads = 4 warps (2x2), warp tile 64x64.
// A smem [m][k] stride 20 (conflict-free ldmatrix, as validated).
// B smem [k][n] stride 136 (8k+n bank map -> conflict-free scalar LDS frags).
// Inputs NOT pre-rounded to tf32 (HW truncates inside MMA).
// EPI: 0 = none, 1 = bias+GELU(exact), 2 = bias+residual, 3 = residual
// ---------------------------------------------------------------------------
#define SA    20
#define SB    136
#define STAGE_F (128 * SA + 16 * SB)           // floats per stage: 4736
#define G2_SMEM (3 * STAGE_F * 4)              // 56832 bytes

template <int EPI>
__global__ __launch_bounds__(128, 2) void mma_gemm(
    const float* __restrict__ A, const float* __restrict__ B,
    float* __restrict__ C, int M, int N, int K,
    const float* __restrict__ bias, const float* __restrict__ resid)
{
    extern __shared__ __align__(16) float sm[];
    const unsigned sbase = (unsigned)__cvta_generic_to_shared(sm);

    const int tid  = threadIdx.x;
    const int lane = tid & 31;
    const int warp = tid >> 5;
    const int bx = blockIdx.x, by = blockIdx.y;
    const int wm = (warp >> 1) * 64;
    const int wn = (warp & 1) * 64;

    float acc[4][8][4];
#pragma unroll
    for (int i = 0; i < 4; i++)
#pragma unroll
        for (int j = 0; j < 8; j++)
#pragma unroll
            for (int t = 0; t < 4; t++) acc[i][j][t] = 0.f;

    const float* Ab = A + (size_t)(by * 128) * K;
    const float* Bb = B + bx * 128;

    // Issue one stage's async copies (A: 128x16, B: 16x128, 16B chunks)
    auto ISSUE = [&](int kt, int stg) {
        unsigned as = sbase + (unsigned)(stg * STAGE_F) * 4u;
        unsigned bs = as + 128 * SA * 4u;
#pragma unroll
        for (int i = 0; i < 4; i++) {
            int c = tid + 128 * i;
            int row = c >> 2, kq = (c & 3) << 2;
            cp16(as + (row * SA + kq) * 4u,
                 Ab + (size_t)row * K + kt * 16 + kq);
        }
#pragma unroll
        for (int i = 0; i < 4; i++) {
            int c = tid + 128 * i;
            int kr = c >> 5, n4 = (c & 31) << 2;
            cp16(bs + (kr * SB + n4) * 4u,
                 Bb + (size_t)(kt * 16 + kr) * N + n4);
        }
        cp_commit();
    };

    auto COMPUTE = [&](int stg) {
        const float* as = sm + stg * STAGE_F;
        const float* bs = as + 128 * SA;
#pragma unroll
        for (int k8 = 0; k8 < 2; k8++) {
            unsigned af[4][4];
            int koff = k8 * 8 + (lane >> 4) * 4;
#pragma unroll
            for (int mt = 0; mt < 4; mt++)
                ldmx4(af[mt], as + (wm + mt * 16 + (lane & 15)) * SA + koff);
            unsigned bf[8][2];
            int krow = k8 * 8 + (lane & 3);
            int ncol = wn + (lane >> 2);
#pragma unroll
            for (int nt = 0; nt < 8; nt++) {
                bf[nt][0] = __float_as_uint(bs[(krow)     * SB + ncol + nt * 8]);
                bf[nt][1] = __float_as_uint(bs[(krow + 4) * SB + ncol + nt * 8]);
            }
#pragma unroll
            for (int mt = 0; mt < 4; mt++)
#pragma unroll
                for (int nt = 0; nt < 8; nt++)
                    mma_tf32(acc[mt][nt], af[mt], bf[nt][0], bf[nt][1]);
        }
    };

    const int KT = K >> 4;
    ISSUE(0, 0);
    ISSUE(1, 1);
    for (int kt = 0; kt < KT; kt++) {
        int stg = kt % 3;
        cp_wait1();
        __syncthreads();
        if (kt + 2 < KT) ISSUE(kt + 2, (kt + 2) % 3);
        else cp_commit();   // keep group count invariant
        COMPUTE(stg);
    }

    // Epilogue
#pragma unroll
    for (int mt = 0; mt < 4; mt++) {
#pragma unroll
        for (int nt = 0; nt < 8; nt++) {
            int r = by * 128 + wm + mt * 16 + (lane >> 2);
            int c = bx * 128 + wn + nt * 8 + (lane & 3) * 2;
#pragma unroll
            for (int half = 0; half < 2; half++) {
                int rr = r + half * 8;
                float v0 = acc[mt][nt][half * 2 + 0];
                float v1 = acc[mt][nt][half * 2 + 1];
                if (EPI == 1) {
                    v0 = gelu_f(v0 + bias[c]);
                    v1 = gelu_f(v1 + bias[c + 1]);
                } else if (EPI == 2) {
                    v0 += bias[c]     + resid[(size_t)rr * N + c];
                    v1 += bias[c + 1] + resid[(size_t)rr * N + c + 1];
                } else if (EPI == 3) {
                    v0 += resid[(size_t)rr * N + c];
                    v1 += resid[(size_t)rr * N + c + 1];
                }
                float2 o = {v0, v1};
                *(float2*)&C[(size_t)rr * N + c] = o;
            }
        }
    }
}

// ---------------------------------------------------------------------------
// Tensor-core causal flash attention (tf32 m16n8k8) — unchanged from R7.
// ---------------------------------------------------------------------------
#define FST 68
#define FSM_Q  0
#define FSM_K  (64 * FST)
#define FSM_V  (2 * 64 * FST)
#define FSM_P  (3 * 64 * FST)
#define FSM_TOT ((3 * 64 + 4 * 16) * FST * 4)   // bytes = 69632

__global__ __launch_bounds__(128) void flash_mma(
    const float* __restrict__ qkv, float* __restrict__ out)
{
    extern __shared__ __align__(16) float fsm[];
    float* Qs = fsm + FSM_Q;
    float* Ks = fsm + FSM_K;
    float* Vt = fsm + FSM_V;

    const int bh = blockIdx.y;
    const int b = bh >> 4, h = bh & 15;
    const int q0 = blockIdx.x * 64;
    const int tid = threadIdx.x, warp = tid >> 5, lane = tid & 31;
    float* Ps = fsm + FSM_P + warp * 16 * FST;
    const float* base = qkv + (size_t)b * SEQ * 3 * DMODEL + h * HEADD;

    for (int i = tid; i < 64 * 16; i += 128) {
        int r = i >> 4, c = (i & 15) << 2;
        float4 v = *(const float4*)(base + (size_t)(q0 + r) * (3 * DMODEL) + c);
        float* d = &Qs[r * FST + c];
        d[0] = __uint_as_float(f2tf32(v.x * 0.125f));
        d[1] = __uint_as_float(f2tf32(v.y * 0.125f));
        d[2] = __uint_as_float(f2tf32(v.z * 0.125f));
        d[3] = __uint_as_float(f2tf32(v.w * 0.125f));
    }

    float O[8][4];
#pragma unroll
    for (int i = 0; i < 8; i++)
#pragma unroll
        for (int t = 0; t < 4; t++) O[i][t] = 0.f;
    float m[2] = {-1e30f, -1e30f};
    float l[2] = {0.f, 0.f};

    const int ntiles = q0 / 64 + 1;
    for (int kvb = 0; kvb < ntiles; kvb++) {
        const int k0 = kvb * 64;
        __syncthreads();
        for (int i = tid; i < 64 * 16; i += 128) {
            int r = i >> 4, c = (i & 15) << 2;
            const float* kr = base + (size_t)(k0 + r) * (3 * DMODEL) + DMODEL + c;
            float4 kv4 = *(const float4*)kr;
            float* kd = &Ks[r * FST + c];
            kd[0] = __uint_as_float(f2tf32(kv4.x));
            kd[1] = __uint_as_float(f2tf32(kv4.y));
            kd[2] = __uint_as_float(f2tf32(kv4.z));
            kd[3] = __uint_as_float(f2tf32(kv4.w));
            float4 vv = *(const float4*)(kr + DMODEL);
            Vt[(c + 0) * FST + r] = __uint_as_float(f2tf32(vv.x));
            Vt[(c + 1) * FST + r] = __uint_as_float(f2tf32(vv.y));
            Vt[(c + 2) * FST + r] = __uint_as_float(f2tf32(vv.z));
            Vt[(c + 3) * FST + r] = __uint_as_float(f2tf32(vv.w));
        }
        __syncthreads();

        float S[8][4];
#pragma unroll
        for (int i = 0; i < 8; i++)
#pragma unroll
            for (int t = 0; t < 4; t++) S[i][t] = 0.f;
#pragma unroll
        for (int k8 = 0; k8 < 8; k8++) {
            unsigned af[4], bf[4];
            int koff = k8 * 8 + (lane >> 4) * 4;
            ldmx4(af, Qs + (warp * 16 + (lane & 15)) * FST + koff);
#pragma unroll
            for (int p = 0; p < 4; p++) {
                ldmx4(bf, Ks + (p * 16 + (lane & 15)) * FST + koff);
                mma_tf32(S[2 * p],     af, bf[0], bf[2]);
                mma_tf32(S[2 * p + 1], af, bf[1], bf[3]);
            }
        }

        const bool diag = (k0 == q0);
        const int cb = 2 * (lane & 3);
#pragma unroll
        for (int half = 0; half < 2; half++) {
            int qrow = q0 + warp * 16 + (lane >> 2) + half * 8;
            if (diag) {
#pragma unroll
                for (int nt = 0; nt < 8; nt++) {
#pragma unroll
                    for (int j = 0; j < 2; j++) {
                        if (k0 + nt * 8 + cb + j > qrow)
                            S[nt][half * 2 + j] = -1e30f;
                    }
                }
            }
            float mx = -1e30f;
#pragma unroll
            for (int nt = 0; nt < 8; nt++)
                mx = fmaxf(mx, fmaxf(S[nt][half * 2], S[nt][half * 2 + 1]));
            mx = fmaxf(mx, __shfl_xor_sync(0xffffffffu, mx, 1));
            mx = fmaxf(mx, __shfl_xor_sync(0xffffffffu, mx, 2));
            float mnew  = fmaxf(m[half], mx);
            float alpha = __expf(m[half] - mnew);
            m[half] = mnew;
            float ps = 0.f;
#pragma unroll
            for (int nt = 0; nt < 8; nt++) {
#pragma unroll
                for (int j = 0; j < 2; j++) {
                    float p = __expf(S[nt][half * 2 + j] - mnew);
                    S[nt][half * 2 + j] = p;
                    ps += p;
                }
            }
            ps += __shfl_xor_sync(0xffffffffu, ps, 1);
            ps += __shfl_xor_sync(0xffffffffu, ps, 2);
            l[half] = l[half] * alpha + ps;
#pragma unroll
            for (int nt = 0; nt < 8; nt++) {
                O[nt][half * 2]     *= alpha;
                O[nt][half * 2 + 1] *= alpha;
            }
        }

#pragma unroll
        for (int half = 0; half < 2; half++) {
            int r = (lane >> 2) + half * 8;
#pragma unroll
            for (int nt = 0; nt < 8; nt++) {
                Ps[r * FST + nt * 8 + cb]     = __uint_as_float(f2tf32(S[nt][half * 2]));
                Ps[r * FST + nt * 8 + cb + 1] = __uint_as_float(f2tf32(S[nt][half * 2 + 1]));
            }
        }
        __syncwarp();

#pragma unroll
        for (int k8 = 0; k8 < 8; k8++) {
            unsigned af[4], bf[4];
            int koff = k8 * 8 + (lane >> 4) * 4;
            ldmx4(af, Ps + (lane & 15) * FST + koff);
#pragma unroll
            for (int p = 0; p < 4; p++) {
                ldmx4(bf, Vt + (p * 16 + (lane & 15)) * FST + koff);
                mma_tf32(O[2 * p],     af, bf[0], bf[2]);
                mma_tf32(O[2 * p + 1], af, bf[1], bf[3]);
            }
        }
    }

#pragma unroll
    for (int half = 0; half < 2; half++) {
        float inv = 1.0f / l[half];
        int q = q0 + warp * 16 + (lane >> 2) + half * 8;
        float* orow = out + (size_t)(b * SEQ + q) * DMODEL + h * HEADD;
#pragma unroll
        for (int nt = 0; nt < 8; nt++) {
            float2 o = {O[nt][half * 2] * inv, O[nt][half * 2 + 1] * inv};
            *(float2*)&orow[nt * 8 + 2 * (lane & 3)] = o;
        }
    }
}

// ---------------------------------------------------------------------------
// Launch pipeline
// ---------------------------------------------------------------------------
extern "C" void kernel_launch(void* const* d_in, const int* in_sizes, int n_in,
                              void* d_out, int out_size)
{
    const float* x      = (const float*)d_in[0];
    const float* w_qkv  = (const float*)d_in[1];
    const float* w_proj = (const float*)d_in[2];
    const float* ln1_w  = (const float*)d_in[3];
    const float* ln1_b  = (const float*)d_in[4];
    const float* ln2_w  = (const float*)d_in[5];
    const float* ln2_b  = (const float*)d_in[6];
    const float* fc1_w  = (const float*)d_in[7];
    const float* fc1_b  = (const float*)d_in[8];
    const float* fc2_w  = (const float*)d_in[9];
    const float* fc2_b  = (const float*)d_in[10];
    float* out = (float*)d_out;

    float *ln1o, *qkv, *attn, *x1, *ln2o, *fc1o;
    cudaGetSymbolAddress((void**)&ln1o, g_ln1);
    cudaGetSymbolAddress((void**)&qkv,  g_qkv);
    cudaGetSymbolAddress((void**)&attn, g_attn);
    cudaGetSymbolAddress((void**)&x1,   g_x1);
    cudaGetSymbolAddress((void**)&ln2o, g_ln2);
    cudaGetSymbolAddress((void**)&fc1o, g_fc1);

    static bool attr_set = false;
    if (!attr_set) {
        cudaFuncSetAttribute(flash_mma,
            cudaFuncAttributeMaxDynamicSharedMemorySize, FSM_TOT);
        cudaFuncSetAttribute(mma_gemm<0>,
            cudaFuncAttributeMaxDynamicSharedMemorySize, G2_SMEM);
        cudaFuncSetAttribute(mma_gemm<1>,
            cudaFuncAttributeMaxDynamicSharedMemorySize, G2_SMEM);
        cudaFuncSetAttribute(mma_gemm<2>,
            cudaFuncAttributeMaxDynamicSharedMemorySize, G2_SMEM);
        cudaFuncSetAttribute(mma_gemm<3>,
            cudaFuncAttributeMaxDynamicSharedMemorySize, G2_SMEM);
        attr_set = true;
    }

    // 1. ln1 = LN(x)
    ln_kernel<<<MROWS, 256>>>(x, ln1_w, ln1_b, ln1o);
    // 2. qkv = ln1 @ w_qkv          [4096,3072]
    mma_gemm<0><<<dim3(3 * DMODEL / 128, MROWS / 128), 128, G2_SMEM>>>(
        ln1o, w_qkv, qkv, MROWS, 3 * DMODEL, DMODEL, nullptr, nullptr);
    // 3. attn = causal_flash(qkv)   [4096,1024]
    flash_mma<<<dim3(SEQ / 64, BATCH * NHEAD), 128, FSM_TOT>>>(qkv, attn);
    // 4. x1 = x + attn @ w_proj
    mma_gemm<3><<<dim3(DMODEL / 128, MROWS / 128), 128, G2_SMEM>>>(
        attn, w_proj, x1, MROWS, DMODEL, DMODEL, nullptr, x);
    // 5. ln2 = LN(x1)
    ln_kernel<<<MROWS, 256>>>(x1, ln2_w, ln2_b, ln2o);
    // 6. fc1 = gelu(ln2 @ fc1_w + fc1_b)   [4096,4096]
    mma_gemm<1><<<dim3(DFF / 128, MROWS / 128), 128, G2_SMEM>>>(
        ln2o, fc1_w, fc1o, MROWS, DFF, DMODEL, fc1_b, nullptr);
    // 7. out = x1 + fc1 @ fc2_w + fc2_b
    mma_gemm<2><<<dim3(DMODEL / 128, MROWS / 128), 128, G2_SMEM>>>(
        fc1o, fc2_w, out, MROWS, DMODEL, DFF, fc2_b, x1);
}